// round 17
// baseline (speedup 1.0000x reference)
#include <cuda_runtime.h>
#include <cstdint>
#include <cstddef>

// out[b] = weight[b] + top1000_scatter_mask(|difference[b]|), B=64, N=1M/batch.
// R17 = R16 + deeper MLP: 4 float4 per thread (16 elements), all 8 independent
// LDG.128 front-batched (MLP_p1 = 8). Grid 16384 blocks.

namespace {

constexpr int B      = 64;
constexpr int NPB    = 1 << 20;
constexpr int TOPN   = 1000;
constexpr unsigned CUT = 0x404CCCCDu; // float bits of 3.2f (rank-1000 ~3.29 sigma)
constexpr int BPB    = 256;           // blocks per batch (4096 elems per block)
constexpr int DCAP   = 16384;         // dense candidate capacity (mean ~1374)
constexpr int SCAP   = 2048;          // smem stage capacity (mean fill ~5.6)
constexpr int CACHE  = 4096;          // k_select smem candidate cache
constexpr int NBIN   = 1024;          // smem hist bins: (key - CUT) >> 14, clamped
constexpr int BCAP   = 512;           // boundary-bin capacity (mean ~13)
constexpr int MAXTIES = 256;
constexpr int STH    = 1024;

__device__ uint2    g_cand[B][DCAP];  // .x = key, .y = idx
__device__ unsigned g_dcnt[B * 32];   // 128B-padded; reset by k_select each replay

__device__ __forceinline__ unsigned keybin(unsigned key) {
    unsigned d = key - CUT;
    unsigned bi = d >> 14;
    return bi < (unsigned)NBIN ? bi : (unsigned)(NBIN - 1);
}

__device__ __forceinline__ void scatter1(float* p) {
    atomicAdd(p, 1.0f);               // result unused -> RED.E.ADD.F32 (REDG)
}

// Streaming pass: out = weight; gather |diff| >= 3.2 into dense per-batch arrays.
// 4 float4 per thread; all 8 independent loads issued before dependent work.
__global__ void __launch_bounds__(256) k_main(const float4* __restrict__ diff,
                                              const float4* __restrict__ w,
                                              float4* __restrict__ out) {
    __shared__ uint2    s_kv[SCAP];
    __shared__ unsigned s_n, s_base;
    unsigned tid = threadIdx.x;
    if (tid == 0) s_n = 0u;
    __syncthreads();

    unsigned b    = blockIdx.x & 63u;            // interleaved batch mapping
    unsigned bblk = blockIdx.x >> 6;             // 0..255
    unsigned base = (b << 18) + bblk * 1024u;    // float4 index of block start

    unsigned t0 = base + tid;
    unsigned t1 = t0 + 256u;
    unsigned t2 = t0 + 512u;
    unsigned t3 = t0 + 768u;

    // Front-batched independent loads (MLP_p1 = 8)
    float4 d0 = __ldcs(&diff[t0]);
    float4 d1 = __ldcs(&diff[t1]);
    float4 d2 = __ldcs(&diff[t2]);
    float4 d3 = __ldcs(&diff[t3]);
    float4 w0 = __ldcs(&w[t0]);
    float4 w1 = __ldcs(&w[t1]);
    float4 w2 = __ldcs(&w[t2]);
    float4 w3 = __ldcs(&w[t3]);
    __stcs(&out[t0], w0);
    __stcs(&out[t1], w1);
    __stcs(&out[t2], w2);
    __stcs(&out[t3], w3);

    unsigned ebase = (bblk * 1024u + tid) << 2;  // element idx of d0.x in batch

    float4 dd[4] = {d0, d1, d2, d3};
#pragma unroll
    for (int q = 0; q < 4; ++q) {
        unsigned eq = ebase + (unsigned)q * 1024u;  // 256 float4 * 4 elems
        unsigned kk[4] = {__float_as_uint(dd[q].x) & 0x7FFFFFFFu,
                          __float_as_uint(dd[q].y) & 0x7FFFFFFFu,
                          __float_as_uint(dd[q].z) & 0x7FFFFFFFu,
                          __float_as_uint(dd[q].w) & 0x7FFFFFFFu};
#pragma unroll
        for (int j = 0; j < 4; ++j) {
            if (kk[j] >= CUT) {                  // ~0.137% of elements
                unsigned p = atomicAdd(&s_n, 1u);
                if (p < (unsigned)SCAP) {
                    s_kv[p] = make_uint2(kk[j], eq + j);
                } else {
                    // Spill (unreachable for N(0,1); correct for any data).
                    unsigned slot = atomicAdd(&g_dcnt[b * 32], 1u);
                    if (slot < (unsigned)DCAP)
                        g_cand[b][slot] = make_uint2(kk[j], eq + j);
                }
            }
        }
    }
    __syncthreads();

    unsigned n = s_n;
    if (n > (unsigned)SCAP) n = (unsigned)SCAP;
    if (n) {
        if (tid == 0)
            s_base = atomicAdd(&g_dcnt[b * 32], n);
        __syncthreads();
        unsigned bs = s_base;
        for (unsigned i = tid; i < n; i += 256u) {
            unsigned slot = bs + i;
            if (slot < (unsigned)DCAP) g_cand[b][slot] = s_kv[i];
        }
    }

    cudaTriggerProgrammaticLaunchCompletion();
}

// Per-batch selection, fully self-contained in SMEM. One block per batch.
__global__ void __launch_bounds__(STH) k_select(const float* __restrict__ diff,
                                                float* __restrict__ out,
                                                const int* __restrict__ ep) {
    __shared__ uint2    s_kv[CACHE];
    __shared__ unsigned hist[NBIN];
    __shared__ unsigned s_wsum[32], s_wsuf[32];
    __shared__ unsigned s_bkey[BCAP];
    __shared__ unsigned s_bidx[BCAP];
    __shared__ unsigned s_bn, s_p0, s_rem;
    __shared__ unsigned s_prefix, s_rem2, s_tcnt;
    __shared__ unsigned s_tidx[MAXTIES];

    int b = blockIdx.x;
    unsigned tid  = threadIdx.x;
    unsigned lane = tid & 31u;
    unsigned wid  = tid >> 5;

    // ---- Preamble overlaps k_main's drain (PDL) ----
    int epoch = ep[0];
    bool hot = (epoch > 1000) && (epoch < 18000) && (epoch % 200 == 0);
    hist[tid] = 0u;
    if (tid == 0) s_bn = 0u;

    cudaGridDependencySynchronize();

    unsigned raw = g_dcnt[b * 32];
    bool fast = (raw >= (unsigned)TOPN) && (raw <= (unsigned)DCAP);
    bool sfit = fast && (raw <= (unsigned)CACHE);
    size_t gbase = (size_t)b * (size_t)NPB;
    unsigned dom = fast ? raw : (unsigned)NPB;

    bool done = !hot;

    if (hot && fast) {
        // ---- Pass A: load candidates once, stash, build smem hist ----
        __syncthreads();
        for (unsigned i = tid; i < dom; i += STH) {
            uint2 kv = g_cand[b][i];
            if (sfit) s_kv[i] = kv;
            atomicAdd(&hist[keybin(kv.x)], 1u);
        }
        __syncthreads();

        // ---- Suffix scan over 1024 bins: 1 bin per thread ----
        unsigned P = hist[tid];
        unsigned s = P;
#pragma unroll
        for (unsigned off = 1; off < 32; off <<= 1) {
            unsigned v = __shfl_down_sync(0xFFFFFFFFu, s, off);
            if (lane + off < 32u) s += v;
        }
        if (lane == 0) s_wsum[wid] = s;
        __syncthreads();
        if (wid == 0) {
            unsigned tsum = s_wsum[lane];
            unsigned ss = tsum;
#pragma unroll
            for (unsigned off = 1; off < 32; off <<= 1) {
                unsigned v = __shfl_down_sync(0xFFFFFFFFu, ss, off);
                if (lane + off < 32u) ss += v;
            }
            s_wsuf[lane] = ss - tsum;
        }
        __syncthreads();
        unsigned above = (s + s_wsuf[wid]) - P;
        if (above < (unsigned)TOPN && above + P >= (unsigned)TOPN) {
            s_p0 = tid; s_rem = (unsigned)TOPN - above;
        }
        __syncthreads();

        unsigned p0  = s_p0;
        unsigned rem = s_rem;
        unsigned m   = hist[p0];

        if (m <= (unsigned)BCAP) {
            // ---- Pass B: REDG-scatter winners, collect boundary bin ----
            for (unsigned i = tid; i < dom; i += STH) {
                uint2 kv = sfit ? s_kv[i] : g_cand[b][i];
                unsigned bi = keybin(kv.x);
                if (bi > p0) {
                    scatter1(&out[gbase + kv.y]);
                } else if (bi == p0) {
                    unsigned p = atomicAdd(&s_bn, 1u);
                    s_bkey[p] = kv.x;                    // p < m <= BCAP
                    s_bidx[p] = kv.y;
                }
            }
            __syncthreads();
            // ---- Exact boundary ranking (key desc, idx asc) ----
            for (unsigned u = tid; u < m; u += STH) {
                unsigned mk = s_bkey[u], mi = s_bidx[u];
                unsigned rank = 0u;
                for (unsigned j = 0; j < m; ++j) {
                    unsigned kj = s_bkey[j];
                    rank += (kj > mk || (kj == mk && s_bidx[j] < mi)) ? 1u : 0u;
                }
                if (rank < rem) scatter1(&out[gbase + mi]);
            }
            done = true;
        }
        __syncthreads();
    }

    if (!done) {
        // ==== Fallback: exact 4-round radix select over full batch ====
        if (tid == 0) { s_prefix = 0u; s_rem2 = (unsigned)TOPN; s_tcnt = 0u; }
        __syncthreads();

        auto getkey = [&](unsigned i) -> unsigned {
            if (fast) return g_cand[b][i].x;
            return __float_as_uint(diff[gbase + i]) & 0x7FFFFFFFu;
        };
        auto getidx = [&](unsigned i) -> unsigned {
            if (fast) return g_cand[b][i].y;
            return i;
        };

        const int      SH[4] = {23, 15, 7, 0};
        const unsigned BM[4] = {255u, 255u, 255u, 127u};
#pragma unroll 1
        for (int r = 0; r < 4; ++r) {
            if (tid < 256u) hist[tid] = 0u;
            __syncthreads();
            int      sh     = SH[r];
            int      hish   = sh + (r == 3 ? 7 : 8);
            unsigned prefix = s_prefix;
            for (unsigned i = tid; i < dom; i += STH) {
                unsigned key = getkey(i);
                if (((key ^ prefix) >> hish) == 0u)
                    atomicAdd(&hist[(key >> sh) & BM[r]], 1u);
            }
            __syncthreads();
            if (tid == 0) {
                unsigned need = s_rem2, acc = 0u;
                int bin = (int)BM[r];
                for (; bin > 0; --bin) {
                    unsigned c = hist[bin];
                    if (acc + c >= need) break;
                    acc += c;
                }
                s_rem2   = need - acc;
                s_prefix = prefix | ((unsigned)bin << sh);
            }
            __syncthreads();
        }

        unsigned thr = s_prefix;
        unsigned req = s_rem2;

        for (unsigned i = tid; i < dom; i += STH) {
            unsigned key = getkey(i);
            if (key > thr) {
                scatter1(&out[gbase + getidx(i)]);
            } else if (key == thr) {
                unsigned p = atomicAdd(&s_tcnt, 1u);
                if (p < (unsigned)MAXTIES) s_tidx[p] = getidx(i);
            }
        }
        __syncthreads();

        unsigned tc = s_tcnt;
        if (tc <= (unsigned)MAXTIES) {
            for (unsigned u = tid; u < tc; u += STH) {
                unsigned my = s_tidx[u], rank = 0u;
                for (unsigned j = 0; j < tc; ++j) rank += (s_tidx[j] < my) ? 1u : 0u;
                if (rank < req) scatter1(&out[gbase + my]);
            }
        } else {
            for (unsigned i = tid; i < dom; i += STH) {
                unsigned key = getkey(i);
                if (key != thr) continue;
                unsigned idx = getidx(i), rank = 0u;
                for (unsigned j = 0; j < dom; ++j) {
                    if (getkey(j) == thr && getidx(j) < idx) ++rank;
                }
                if (rank < req) scatter1(&out[gbase + idx]);
            }
        }
        __syncthreads();
    }

    if (tid == 0) g_dcnt[b * 32] = 0u;   // reset for next graph replay
}

} // namespace

extern "C" void kernel_launch(void* const* d_in, const int* in_sizes, int n_in,
                              void* d_out, int out_size) {
    const float* diff = (const float*)d_in[0];
    const float* w    = (const float*)d_in[1];
    const int*   ep   = (const int*)d_in[2];
    float*       out  = (float*)d_out;

    k_main<<<B * BPB, 256>>>((const float4*)diff, (const float4*)w, (float4*)out);

    cudaLaunchConfig_t cfg = {};
    cfg.gridDim  = dim3(B);
    cfg.blockDim = dim3(STH);
    cfg.stream   = 0;
    cudaLaunchAttribute attr[1];
    attr[0].id = cudaLaunchAttributeProgrammaticStreamSerialization;
    attr[0].val.programmaticStreamSerializationAllowed = 1;
    cfg.attrs    = attr;
    cfg.numAttrs = 1;
    cudaLaunchKernelEx(&cfg, k_select, diff, out, ep);
}